// round 10
// baseline (speedup 1.0000x reference)
#include <cuda_runtime.h>
#include <cuda_fp16.h>
#include <cstdint>

// EEG_GAT_65901978190358 — round 10
// R9 + L1-wavefront reductions:
//  1) coalesced A loads (warp-per-row-chunk: 1 LDG.64 = one contiguous 256B row segment)
//  2) smem-staged epilogue (swizzled STS.64, then coalesced LDS.32 + STG.32)
// Attention stays fused into block 0, reading the staged smem tile.

#define FDIM  250
#define BM    64
#define BN    256
#define BKF   64            // k-values (floats/halves) per chunk; 128 B per smem row
#define NCHUNK 4
#define NEG_SLOPE 0.2f

__device__ __align__(16) __half g_Bh[NCHUNK * 256 * BKF];  // pre-swizzled SMEM image of W^T (fp16)

// ---------------- helpers ----------------
__device__ __forceinline__ uint32_t smem_u32(const void* p) {
    uint32_t a;
    asm("{ .reg .u64 t; cvta.to.shared.u64 t, %1; cvt.u32.u64 %0, t; }" : "=r"(a) : "l"(p));
    return a;
}
__device__ __forceinline__ uint32_t pack_f16x2(float lo, float hi) {
    uint32_t r;
    asm("cvt.rn.f16x2.f32 %0, %1, %2;" : "=r"(r) : "f"(hi), "f"(lo));
    return r;
}
__device__ __forceinline__ void sts_b32(uint32_t addr, uint32_t v) {
    asm volatile("st.shared.b32 [%0], %1;" :: "r"(addr), "r"(v) : "memory");
}
__device__ __forceinline__ void cp_async16(uint32_t smem_addr, const void* gptr) {
    asm volatile("cp.async.cg.shared.global [%0], [%1], 16;" :: "r"(smem_addr), "l"(gptr) : "memory");
}
__device__ __forceinline__ void ldmx4(uint32_t* r, uint32_t addr) {
    asm volatile("ldmatrix.sync.aligned.m8n8.x4.shared.b16 {%0,%1,%2,%3}, [%4];"
                 : "=r"(r[0]), "=r"(r[1]), "=r"(r[2]), "=r"(r[3]) : "r"(addr));
}
__device__ __forceinline__ void mma_f16(float* c, const uint32_t* a, uint32_t b0, uint32_t b1) {
    asm volatile(
        "mma.sync.aligned.m16n8k16.row.col.f32.f16.f16.f32 "
        "{%0,%1,%2,%3}, {%4,%5,%6,%7}, {%8,%9}, {%0,%1,%2,%3};"
        : "+f"(c[0]), "+f"(c[1]), "+f"(c[2]), "+f"(c[3])
        : "r"(a[0]), "r"(a[1]), "r"(a[2]), "r"(a[3]), "r"(b0), "r"(b1));
}
// swizzled byte offset for the fp32 staging tile: row pitch 1024 B,
// 16B chunks XORed with (row & 7) inside each 128 B segment.
__device__ __forceinline__ int sw_off(int r, int j) {  // j in floats
    return r * 1024 + ((j >> 5) << 7) + ((((j >> 2) & 7) ^ (r & 7)) << 4) + ((j & 3) << 2);
}

// ---------------- prep: g_Bh = pre-swizzled fp16 SMEM image of W^T ----------------
__global__ void prep_Bh(const float* __restrict__ W) {
    int idx = blockIdx.x * 256 + threadIdx.x;      // 65536 total
    int c  = idx >> 14;
    int n  = (idx >> 6) & 255;
    int kk = idx & 63;
    int k  = c * BKF + kk;
    float v = (n < FDIM && k < FDIM) ? W[k * FDIM + n] : 0.f;
    int dst = n * BKF + (kk & 7) + 8 * ((kk >> 3) ^ (n & 7));
    g_Bh[c * (256 * BKF) + dst] = __float2half_rn(v);
}

// ---------------- main GEMM + fused block-0 attention ----------------
__global__ __launch_bounds__(256, 2)
void gemm_h16(const float* __restrict__ X, const float* __restrict__ bias,
              const float* __restrict__ att_src, const float* __restrict__ att_dst,
              float* __restrict__ out, int nrows) {
    extern __shared__ __align__(16) char dsmem[];
    __shared__ float s_bias[256];
    __shared__ float s_as[64];
    __shared__ float s_ad[64];
    __shared__ float s_alpha[8][64];

    const int tid  = threadIdx.x;
    const int wid  = tid >> 5, lane = tid & 31;
    const int q    = lane >> 2, tig = lane & 3;
    const int wr   = wid >> 2, wc = wid & 3;       // warp grid 2 x 4 (m x n)
    const long row0 = (long)blockIdx.x * BM;
    const bool blk0 = (blockIdx.x == 0);

    const uint32_t sb = smem_u32(dsmem);
    const uint32_t Au[2] = { sb,          sb + 8192 };              // 64*128 B each
    const uint32_t Bu[2] = { sb + 16384,  sb + 16384 + 32768 };     // 256*128 B each

    s_bias[tid] = (tid < FDIM) ? bias[tid] : 0.f;

    // A loader: warp per 8 rows, lane covers float2 at k = 2*lane within chunk
    const float* xbase = X + (row0 + wid * 8) * FDIM + 2 * lane;

    // ldmatrix per-lane geometry
    const int a_mrow = ((lane >> 3) & 1) * 8 + (lane & 7);
    const int a_chb  = (lane >> 4);
    const int b_nrow = (lane >> 4) * 8 + (lane & 7);
    const int b_chb  = ((lane >> 3) & 1);

    float acc[2][8][4];
    #pragma unroll
    for (int mt = 0; mt < 2; ++mt)
        #pragma unroll
        for (int nt = 0; nt < 8; ++nt)
            #pragma unroll
            for (int e = 0; e < 4; ++e) acc[mt][nt][e] = 0.f;

    #define LOAD_B(cc, buf) do {                                                    \
        const char* src = (const char*)g_Bh + (size_t)(cc) * 32768;                  \
        _Pragma("unroll")                                                            \
        for (int v8 = 0; v8 < 8; ++v8) {                                             \
            int i = v8 * 256 + tid;                                                  \
            cp_async16(Bu[buf] + i * 16, src + i * 16);                              \
        }                                                                            \
    } while (0)

    // coalesced: one LDG.64 per row-chunk (256 B contiguous across the warp)
    #define LOAD_A(cc, buf) do {                                                     \
        const int kk = (cc) * BKF + 2 * lane;                                        \
        const bool kok = (kk + 1) < FDIM;                                            \
        _Pragma("unroll")                                                            \
        for (int rr = 0; rr < 8; ++rr) {                                             \
            int r = wid * 8 + rr;                                                    \
            float2 t = make_float2(0.f, 0.f);                                        \
            if (kok && (row0 + r) < nrows)                                           \
                t = *reinterpret_cast<const float2*>(xbase + rr * FDIM + (cc) * BKF);\
            uint32_t hv = pack_f16x2(t.x, t.y);                                      \
            uint32_t addr = Au[buf] + r * 128 +                                      \
                            ((((lane >> 2)) ^ (r & 7)) << 4) + ((lane & 3) << 2);    \
            sts_b32(addr, hv);                                                       \
        }                                                                            \
    } while (0)

    #define COMPUTE(buf) do {                                                        \
        _Pragma("unroll")                                                             \
        for (int g = 0; g < 4; ++g) {                                                 \
            uint32_t a[2][4];                                                         \
            _Pragma("unroll")                                                         \
            for (int mt = 0; mt < 2; ++mt) {                                          \
                int r = wr * 32 + mt * 16 + a_mrow;                                   \
                int ch = 2 * g + a_chb;                                               \
                ldmx4(a[mt], Au[buf] + r * 128 + ((ch ^ (r & 7)) << 4));              \
            }                                                                         \
            _Pragma("unroll")                                                         \
            for (int p = 0; p < 4; ++p) {                                             \
                uint32_t b[4];                                                        \
                int r = wc * 64 + p * 16 + b_nrow;                                    \
                int ch = 2 * g + b_chb;                                               \
                ldmx4(b, Bu[buf] + r * 128 + ((ch ^ (r & 7)) << 4));                  \
                mma_f16(acc[0][2 * p],     a[0], b[0], b[1]);                         \
                mma_f16(acc[0][2 * p + 1], a[0], b[2], b[3]);                         \
                mma_f16(acc[1][2 * p],     a[1], b[0], b[1]);                         \
                mma_f16(acc[1][2 * p + 1], a[1], b[2], b[3]);                         \
            }                                                                         \
        }                                                                             \
    } while (0)

    // ---- pipeline: double-buffered over 4 K-chunks ----
    LOAD_B(0, 0);
    asm volatile("cp.async.commit_group;" ::: "memory");
    LOAD_A(0, 0);
    asm volatile("cp.async.wait_group 0;" ::: "memory");
    __syncthreads();

    #pragma unroll
    for (int c = 0; c < NCHUNK; ++c) {
        int buf = c & 1;
        if (c < NCHUNK - 1) {
            LOAD_B(c + 1, buf ^ 1);
            asm volatile("cp.async.commit_group;" ::: "memory");
            LOAD_A(c + 1, buf ^ 1);
        }
        COMPUTE(buf);
        if (c < NCHUNK - 1) {
            asm volatile("cp.async.wait_group 0;" ::: "memory");
            __syncthreads();
        }
    }

    // ---- epilogue: stage accumulators into swizzled fp32 smem tile ----
    __syncthreads();   // all warps done reading pipeline smem

    #pragma unroll
    for (int mt = 0; mt < 2; ++mt) {
        int r0 = wr * 32 + mt * 16 + q;
        #pragma unroll
        for (int nt = 0; nt < 8; ++nt) {
            int j = wc * 64 + nt * 8 + 2 * tig;    // even
            float* a4 = acc[mt][nt];
            *reinterpret_cast<float2*>(dsmem + sw_off(r0,     j)) = make_float2(a4[0], a4[1]);
            *reinterpret_cast<float2*>(dsmem + sw_off(r0 + 8, j)) = make_float2(a4[2], a4[3]);
        }
    }
    __syncthreads();

    // ---- coalesced smem -> gmem (+bias); rows < 63 handled by block-0 attention ----
    #pragma unroll
    for (int rr = 0; rr < 8; ++rr) {
        int r = wid * 8 + rr;
        long grow = row0 + r;
        if (grow < 63 || grow >= nrows) continue;
        float* orow = out + grow * FDIM;
        #pragma unroll
        for (int i = 0; i < 8; ++i) {
            int col = 32 * i + lane;
            if (col < FDIM)
                orow[col] = *reinterpret_cast<const float*>(dsmem + sw_off(r, col)) + s_bias[col];
        }
    }

    if (!blk0) return;

    // ================= block 0: dense 63x63 attention (h in staged smem) =================
    for (int i = wid; i < 63; i += 8) {
        float s1 = 0.f, s2 = 0.f;
        for (int k = lane; k < FDIM; k += 32) {
            float hv = *reinterpret_cast<const float*>(dsmem + sw_off(i, k));
            s1 += hv * att_src[k];
            s2 += hv * att_dst[k];
        }
        #pragma unroll
        for (int o = 16; o > 0; o >>= 1) {
            s1 += __shfl_xor_sync(0xffffffffu, s1, o);
            s2 += __shfl_xor_sync(0xffffffffu, s2, o);
        }
        if (lane == 0) { s_as[i] = s1; s_ad[i] = s2; }
    }
    __syncthreads();

    for (int j = wid; j < 63; j += 8) {
        float ad = s_ad[j];
        float e0 = s_as[lane] + ad;
        e0 = (e0 >= 0.f) ? e0 : NEG_SLOPE * e0;
        float e1 = -3.4e38f;
        if (lane < 31) {
            e1 = s_as[lane + 32] + ad;
            e1 = (e1 >= 0.f) ? e1 : NEG_SLOPE * e1;
        }
        float m = fmaxf(e0, e1);
        #pragma unroll
        for (int o = 16; o > 0; o >>= 1) m = fmaxf(m, __shfl_xor_sync(0xffffffffu, m, o));
        float x0 = expf(e0 - m);
        float x1 = (lane < 31) ? expf(e1 - m) : 0.f;
        float sum = x0 + x1;
        #pragma unroll
        for (int o = 16; o > 0; o >>= 1) sum += __shfl_xor_sync(0xffffffffu, sum, o);
        float inv = 1.f / sum;
        s_alpha[wid][lane]      = x0 * inv;
        s_alpha[wid][lane + 32] = x1 * inv;
        __syncwarp();

        for (int t = lane; t < FDIM; t += 32) {
            float a = 0.f;
            #pragma unroll
            for (int i = 0; i < 63; ++i)
                a = fmaf(s_alpha[wid][i],
                         *reinterpret_cast<const float*>(dsmem + sw_off(i, t)), a);
            out[(size_t)j * FDIM + t] = a + s_bias[t];
        }
        __syncwarp();
    }
}

extern "C" void kernel_launch(void* const* d_in, const int* in_sizes, int n_in,
                              void* d_out, int out_size) {
    const float* x       = (const float*)d_in[0];
    const float* W       = (const float*)d_in[1];
    const float* att_src = (const float*)d_in[2];
    const float* att_dst = (const float*)d_in[3];
    const float* bias    = (const float*)d_in[4];
    float* out = (float*)d_out;

    const int nrows = in_sizes[0] / FDIM;                 // 258048
    const int smem_dyn = 16384 + 2 * 32768;               // 80 KB (>= 64 KB staging)

    static int configured = 0;
    if (!configured) {
        cudaFuncSetAttribute(gemm_h16, cudaFuncAttributeMaxDynamicSharedMemorySize, smem_dyn);
        configured = 1;
    }

    prep_Bh<<<256, 256>>>(W);
    gemm_h16<<<(nrows + BM - 1) / BM, 256, smem_dyn>>>(x, bias, att_src, att_dst, out, nrows);
}